// round 14
// baseline (speedup 1.0000x reference)
#include <cuda_runtime.h>
#include <cuda_bf16.h>
#include <cstdint>

#define DIMC  512
#define NPOS  256
#define NB    2
#define NTAB  961
#define KDIM  512
#define KC    64                 // bf16 k per chunk = 128 bytes = SW128 row
#define LOG2E 1.4426950408889634f
#define SCALE 0.044194173824159216f   // 512^-0.5
#define DBLK  8
#define GSPLIT 4
#define GCH   (NPOS / GSPLIT)    // 64
#define QSPLIT 2
#define PSPLIT 4

// ---------------- scratch (device globals; no allocs) ----------------
__device__ float  g_qkv  [NB * 3 * DIMC * NPOS];               // [b][o][p] fp32
__device__ float  g_qpart[NB * QSPLIT * 3 * DIMC * NPOS];      // QKV split-K partials
__device__ float  g_part [NB * PSPLIT * DIMC * NPOS];          // proj split-K partials
__device__ float  g_bias [NPOS * NPOS];                        // biasT[g][h]*log2e
__device__ float2 g_pp   [NB * DIMC * NPOS * GSPLIT];          // attn partial (num,den)
__device__ __align__(16) __nv_bfloat16 g_wq_hi[3 * DIMC * KDIM];
__device__ __align__(16) __nv_bfloat16 g_wq_lo[3 * DIMC * KDIM];
__device__ __align__(16) __nv_bfloat16 g_wp_hi[DIMC * KDIM];
__device__ __align__(16) __nv_bfloat16 g_wp_lo[DIMC * KDIM];
__device__ __align__(16) __nv_bfloat16 g_xt_hi[NB * NPOS * KDIM];  // Xt[h][c]
__device__ __align__(16) __nv_bfloat16 g_xt_lo[NB * NPOS * KDIM];
__device__ __align__(16) __nv_bfloat16 g_ot_hi[NB * NPOS * KDIM];  // Ot[h][d]
__device__ __align__(16) __nv_bfloat16 g_ot_lo[NB * NPOS * KDIM];

// ---------------- helpers ----------------
__device__ __forceinline__ uint32_t smem_u32(const void* p) {
    uint32_t a;
    asm("{ .reg .u64 t; cvta.to.shared.u64 t, %1; cvt.u32.u64 %0, t; }" : "=r"(a) : "l"(p));
    return a;
}
#define SWZ128(off) ((off) ^ (((off) >> 3) & 0x70))

__device__ __forceinline__ void ldsm_x4(uint32_t* r, uint32_t addr) {
    asm volatile("ldmatrix.sync.aligned.m8n8.x4.shared.b16 {%0,%1,%2,%3}, [%4];"
                 : "=r"(r[0]), "=r"(r[1]), "=r"(r[2]), "=r"(r[3]) : "r"(addr));
}
__device__ __forceinline__ void mma_bf16(float* d, const uint32_t* a, const uint32_t* b) {
    asm volatile(
        "mma.sync.aligned.m16n8k16.row.col.f32.bf16.bf16.f32 "
        "{%0,%1,%2,%3}, {%4,%5,%6,%7}, {%8,%9}, {%0,%1,%2,%3};"
        : "+f"(d[0]), "+f"(d[1]), "+f"(d[2]), "+f"(d[3])
        : "r"(a[0]), "r"(a[1]), "r"(a[2]), "r"(a[3]), "r"(b[0]), "r"(b[1]));
}

// ---------------- prep: split weights (x4 vec), bias table, transpose x -----
__global__ __launch_bounds__(256) void prep(const float* __restrict__ x,
                                            const float* __restrict__ qkv_w,
                                            const float* __restrict__ proj_w,
                                            const float* __restrict__ rpb) {
    const int blk = blockIdx.x, t = threadIdx.x;
    const int NW1 = (3 * DIMC * KDIM) / 1024;       // 768  (x4 vectorized)
    const int NW2 = NW1 + (DIMC * KDIM) / 1024;     // +256
    const int NW3 = NW2 + (NPOS * NPOS) / 256;      // +256

    if (blk < NW2) {
        const bool isQ = blk < NW1;
        const float* W = isQ ? qkv_w : proj_w;
        __nv_bfloat16* Hi = isQ ? g_wq_hi : g_wp_hi;
        __nv_bfloat16* Lo = isQ ? g_wq_lo : g_wp_lo;
        long i = ((long)(isQ ? blk : blk - NW1) * 256 + t) * 4;
        float4 w = *(const float4*)(W + i);
        __nv_bfloat16 h0 = __float2bfloat16(w.x), h1 = __float2bfloat16(w.y);
        __nv_bfloat16 h2 = __float2bfloat16(w.z), h3 = __float2bfloat16(w.w);
        __nv_bfloat16 hv[4] = {h0, h1, h2, h3};
        __nv_bfloat16 lv[4] = {
            __float2bfloat16(w.x - __bfloat162float(h0)),
            __float2bfloat16(w.y - __bfloat162float(h1)),
            __float2bfloat16(w.z - __bfloat162float(h2)),
            __float2bfloat16(w.w - __bfloat162float(h3))};
        *(uint2*)(Hi + i) = *(const uint2*)hv;
        *(uint2*)(Lo + i) = *(const uint2*)lv;
    } else if (blk < NW3) {
        int i = (blk - NW2) * 256 + t;
        int g = i >> 8, h = i & 255;
        int v = ((h >> 4) - (g >> 4)) + ((h & 15) - (g & 15));
        g_bias[i] = rpb[(v + NTAB) % NTAB] * LOG2E;
    } else {
        // transpose x[b][c][h] -> Xt[b][h][c] (+ hi/lo split)
        int q = blk - NW3;                 // 0..255
        int b = q >> 7;
        int r = q & 127;
        int c0 = (r >> 3) * 32;
        int h0 = (r & 7) * 32;
        __shared__ float tile[32][33];
        int tx = t & 31, ty = t >> 5;
#pragma unroll
        for (int i = 0; i < 4; i++)
            tile[ty + 8 * i][tx] = (x + (long)b * DIMC * NPOS)
                                   [(long)(c0 + ty + 8 * i) * NPOS + h0 + tx];
        __syncthreads();
#pragma unroll
        for (int i = 0; i < 4; i++) {
            int h = h0 + ty + 8 * i, c = c0 + tx;
            float v = tile[tx][ty + 8 * i];
            __nv_bfloat16 hi = __float2bfloat16(v);
            long o = (long)b * NPOS * KDIM + (long)h * KDIM + c;
            g_xt_hi[o] = hi;
            g_xt_lo[o] = __float2bfloat16(v - __bfloat162float(hi));
        }
    }
}

// ---------------- mma.sync GEMM: C[m][n] = sum_k A[m][k]*B[n][k] ------------
#define SA_HI 0
#define SA_LO 8192
#define SB_HI 16384
#define SB_LO 24576

template<int SPLIT>
__global__ __launch_bounds__(256) void mma_gemm(
        const __nv_bfloat16* __restrict__ Ahi, const __nv_bfloat16* __restrict__ Alo,
        const __nv_bfloat16* __restrict__ Bhi, const __nv_bfloat16* __restrict__ Blo,
        long sB, float* __restrict__ C, long sC) {
    __shared__ __align__(1024) char smem[32768];
    const uint32_t sb = smem_u32(smem);
    const int t = threadIdx.x;
    const int lane = t & 31, wid = t >> 5;
    const int wm = wid & 1, wn = wid >> 1;       // 2 (M) x 4 (N)
    const int n0 = blockIdx.x * 64;
    const int m0 = blockIdx.y * 64;
    const int z  = blockIdx.z;
    const int b  = z / SPLIT;
    const int ks0 = z % SPLIT;
    const int nch = (KDIM / KC) / SPLIT;
    const int ch0 = ks0 * nch;

    const __nv_bfloat16* Ah = Ahi + (long)m0 * KDIM;
    const __nv_bfloat16* Al = Alo + (long)m0 * KDIM;
    const __nv_bfloat16* Bh = Bhi + (long)b * sB + (long)n0 * KDIM;
    const __nv_bfloat16* Bl = Blo + (long)b * sB + (long)n0 * KDIM;

    float ahh[2][2][4], ahl[2][2][4], alh[2][2][4];
#pragma unroll
    for (int i = 0; i < 2; i++)
#pragma unroll
        for (int j = 0; j < 2; j++)
#pragma unroll
            for (int r = 0; r < 4; r++) {
                ahh[i][j][r] = 0.f; ahl[i][j][r] = 0.f; alh[i][j][r] = 0.f;
            }

    int rowi[2], jci[2];
    uint32_t dsti[2];
#pragma unroll
    for (int i = 0; i < 2; i++) {
        int id = t + i * 256;
        rowi[i] = id >> 3; jci[i] = id & 7;
        dsti[i] = SWZ128((uint32_t)(rowi[i] * 128 + jci[i] * 16));
    }

    const int a_row  = wm * 32 + (lane & 15);
    const int a_colb = (lane >> 4) << 4;
    const int b_row  = wn * 16 + (lane & 7) + ((lane >> 4) << 3);
    const int b_colb = ((lane >> 3) & 1) << 4;

    uint4 pah[2], pal[2], pbh[2], pbl[2];
#pragma unroll
    for (int i = 0; i < 2; i++) {
        long go = (long)rowi[i] * KDIM + (long)ch0 * KC + jci[i] * 8;
        pah[i] = *(const uint4*)(Ah + go);
        pal[i] = *(const uint4*)(Al + go);
        pbh[i] = *(const uint4*)(Bh + go);
        pbl[i] = *(const uint4*)(Bl + go);
    }

    for (int ch = 0; ch < nch; ch++) {
#pragma unroll
        for (int i = 0; i < 2; i++) {
            *(uint4*)(smem + SA_HI + dsti[i]) = pah[i];
            *(uint4*)(smem + SA_LO + dsti[i]) = pal[i];
            *(uint4*)(smem + SB_HI + dsti[i]) = pbh[i];
            *(uint4*)(smem + SB_LO + dsti[i]) = pbl[i];
        }
        __syncthreads();

        if (ch + 1 < nch) {
            const long kb16 = (long)(ch0 + ch + 1) * KC;
#pragma unroll
            for (int i = 0; i < 2; i++) {
                long go = (long)rowi[i] * KDIM + kb16 + jci[i] * 8;
                pah[i] = *(const uint4*)(Ah + go);
                pal[i] = *(const uint4*)(Al + go);
                pbh[i] = *(const uint4*)(Bh + go);
                pbl[i] = *(const uint4*)(Bl + go);
            }
        }

#pragma unroll
        for (int kq = 0; kq < 4; kq++) {
            const int kb = kq * 32;
            uint32_t ah[2][4], al[2][4], bh[4], bl[4];
#pragma unroll
            for (int mi = 0; mi < 2; mi++) {
                uint32_t off = SWZ128((uint32_t)((a_row + mi * 16) * 128 + kb + a_colb));
                ldsm_x4(ah[mi], sb + SA_HI + off);
                ldsm_x4(al[mi], sb + SA_LO + off);
            }
            {
                uint32_t off = SWZ128((uint32_t)(b_row * 128 + kb + b_colb));
                ldsm_x4(bh, sb + SB_HI + off);
                ldsm_x4(bl, sb + SB_LO + off);
            }
#pragma unroll
            for (int mi = 0; mi < 2; mi++)
#pragma unroll
                for (int nj = 0; nj < 2; nj++) {
                    mma_bf16(ahh[mi][nj], ah[mi], &bh[nj * 2]);
                    mma_bf16(ahl[mi][nj], ah[mi], &bl[nj * 2]);
                    mma_bf16(alh[mi][nj], al[mi], &bh[nj * 2]);
                }
        }
        __syncthreads();
    }

    const int g = lane >> 2, tg = lane & 3;
#pragma unroll
    for (int mi = 0; mi < 2; mi++) {
        int mrow = m0 + wm * 32 + mi * 16 + g;
        float* Crow0 = C + (long)z * sC + (long)mrow * NPOS + n0 + wn * 16;
        float* Crow1 = Crow0 + 8 * NPOS;
#pragma unroll
        for (int nj = 0; nj < 2; nj++) {
            int c = nj * 8 + tg * 2;
            Crow0[c]     = ahh[mi][nj][0] + ahl[mi][nj][0] + alh[mi][nj][0];
            Crow0[c + 1] = ahh[mi][nj][1] + ahl[mi][nj][1] + alh[mi][nj][1];
            Crow1[c]     = ahh[mi][nj][2] + ahl[mi][nj][2] + alh[mi][nj][2];
            Crow1[c + 1] = ahh[mi][nj][3] + ahl[mi][nj][3] + alh[mi][nj][3];
        }
    }
}

// ---------------- deterministic split-K reduce (+bias) ----------------------
template<int SPLIT>
__global__ __launch_bounds__(256) void splitk_reduce(const float* __restrict__ part,
                                                     const float* __restrict__ bias,
                                                     float* __restrict__ out, int Mrows) {
    const long MN = (long)Mrows * NPOS;
    const long idx = ((long)blockIdx.x * 256 + threadIdx.x) * 4;
    const int b  = (int)(idx / MN);
    const long mn = idx - (long)b * MN;
    const int m  = (int)(mn / NPOS);

    const float* p0 = part + ((long)b * SPLIT) * MN + mn;
    float4 s = *(const float4*)p0;
#pragma unroll
    for (int k = 1; k < SPLIT; k++) {
        float4 q = *(const float4*)(p0 + (long)k * MN);
        s.x += q.x; s.y += q.y; s.z += q.z; s.w += q.w;
    }
    float bb = bias[m];
    s.x += bb; s.y += bb; s.z += bb; s.w += bb;
    *(float4*)(out + idx) = s;
}

// ---------------- per-channel attention: g-split partial pass ---------------
// CTA = (d-block of 8, g-chunk of 64, b). Thread h accumulates partial
// (num, den) over its g-chunk for 8 channels.
__global__ __launch_bounds__(256) void chan_attn_part() {
    const int d0 = blockIdx.x * DBLK;
    const int s  = blockIdx.y;
    const int b  = blockIdx.z;
    const int h  = threadIdx.x;
    const int g0 = s * GCH;

    const float* base = g_qkv + (long)b * 3 * DIMC * NPOS;
    __shared__ float2 skv[DBLK][GCH];

    for (int i = h; i < DBLK * GCH; i += 256) {
        int d = i / GCH, gg = i % GCH;
        float kk = base[(long)(DIMC     + d0 + d) * NPOS + g0 + gg];
        float vv = base[(long)(2 * DIMC + d0 + d) * NPOS + g0 + gg];
        skv[d][gg] = make_float2(kk, vv);
    }

    float a[DBLK], num[DBLK], den[DBLK];
#pragma unroll
    for (int d = 0; d < DBLK; d++) {
        a[d]   = base[(long)(d0 + d) * NPOS + h] * (SCALE * LOG2E);
        num[d] = 0.f;
        den[d] = 0.f;
    }
    __syncthreads();

    const float* bp = g_bias + (long)g0 * NPOS + h;
#pragma unroll 4
    for (int gg = 0; gg < GCH; gg++) {
        float bb = __ldg(bp + gg * NPOS);
#pragma unroll
        for (int d = 0; d < DBLK; d++) {
            float2 kv = skv[d][gg];
            float e = exp2f(fmaf(a[d], kv.x, bb));
            num[d] = fmaf(e, kv.y, num[d]);
            den[d] += e;
        }
    }

#pragma unroll
    for (int d = 0; d < DBLK; d++)
        g_pp[(((long)b * DIMC + d0 + d) * NPOS + h) * GSPLIT + s] =
            make_float2(num[d], den[d]);
}

// ---------------- combine partials -> transposed hi/lo bf16 output ----------
// thread = (b, h, group of 8 d). Fixed-order sums (deterministic).
__global__ __launch_bounds__(256) void chan_attn_comb() {
    const int idx = blockIdx.x * 256 + threadIdx.x;     // 0..32767
    const int b  = idx >> 14;
    const int r  = idx & 16383;
    const int h  = r >> 6;
    const int dg = (r & 63) * 8;

    __nv_bfloat16 oh[8], ol[8];
#pragma unroll
    for (int d = 0; d < 8; d++) {
        const float2* p = g_pp + (((long)b * DIMC + dg + d) * NPOS + h) * GSPLIT;
        float num = 0.f, den = 0.f;
#pragma unroll
        for (int s = 0; s < GSPLIT; s++) {
            float2 q = p[s];
            num += q.x; den += q.y;
        }
        float o = num / den;
        oh[d] = __float2bfloat16(o);
        ol[d] = __float2bfloat16(o - __bfloat162float(oh[d]));
    }
    long off = ((long)b * NPOS + h) * KDIM + dg;
    *(uint4*)(g_ot_hi + off) = *(const uint4*)oh;
    *(uint4*)(g_ot_lo + off) = *(const uint4*)ol;
}

// ---------------------------------------------------------------------------
extern "C" void kernel_launch(void* const* d_in, const int* in_sizes, int n_in,
                              void* d_out, int out_size) {
    const float* x      = (const float*)d_in[0];
    const float* qkv_w  = (const float*)d_in[1];
    const float* qkv_b  = (const float*)d_in[2];
    const float* proj_w = (const float*)d_in[3];
    const float* proj_b = (const float*)d_in[4];
    const float* rpb    = (const float*)d_in[5];
    float* out = (float*)d_out;

    float *qkv_ptr, *qpart_ptr, *part_ptr;
    __nv_bfloat16 *wqh, *wql, *wph, *wpl, *xth, *xtl, *oth, *otl;
    cudaGetSymbolAddress((void**)&qkv_ptr,  g_qkv);
    cudaGetSymbolAddress((void**)&qpart_ptr, g_qpart);
    cudaGetSymbolAddress((void**)&part_ptr, g_part);
    cudaGetSymbolAddress((void**)&wqh, g_wq_hi);
    cudaGetSymbolAddress((void**)&wql, g_wq_lo);
    cudaGetSymbolAddress((void**)&wph, g_wp_hi);
    cudaGetSymbolAddress((void**)&wpl, g_wp_lo);
    cudaGetSymbolAddress((void**)&xth, g_xt_hi);
    cudaGetSymbolAddress((void**)&xtl, g_xt_lo);
    cudaGetSymbolAddress((void**)&oth, g_ot_hi);
    cudaGetSymbolAddress((void**)&otl, g_ot_lo);

    // 1) prep: weight split + bias table + x transpose/split
    prep<<<768 + 256 + 256 + 256, 256>>>(x, qkv_w, proj_w, rpb);

    // 2) QKV split-K x2 (384 CTAs) + reduce(+bias) -> g_qkv fp32 [o][p]
    {
        dim3 grid(NPOS / 64, (3 * DIMC) / 64, NB * QSPLIT);  // (4, 24, 4)
        mma_gemm<QSPLIT><<<grid, 256>>>(wqh, wql, xth, xtl,
                                        (long)NPOS * KDIM,
                                        qpart_ptr, (long)3 * DIMC * NPOS);
        splitk_reduce<QSPLIT><<<(NB * 3 * DIMC * NPOS / 4) / 256, 256>>>(
            qpart_ptr, qkv_b, qkv_ptr, 3 * DIMC);
    }

    // 3) per-channel attention: partial (512 CTAs) + combine (128 CTAs)
    {
        dim3 grid(DIMC / DBLK, GSPLIT, NB);                  // (64, 4, 2)
        chan_attn_part<<<grid, 256>>>();
        chan_attn_comb<<<(NB * NPOS * 64) / 256, 256>>>();   // 128 CTAs
    }

    // 4) out = proj_w * Ot^T (+b): split-K x4 (256 CTAs) + reduce
    {
        dim3 grid(NPOS / 64, DIMC / 64, NB * PSPLIT);        // (4, 8, 8)
        mma_gemm<PSPLIT><<<grid, 256>>>(wph, wpl, oth, otl,
                                        (long)NPOS * KDIM,
                                        part_ptr, (long)DIMC * NPOS);
        splitk_reduce<PSPLIT><<<(NB * DIMC * NPOS / 4) / 256, 256>>>(
            part_ptr, proj_b, out, DIMC);
    }
}

// round 15
// speedup vs baseline: 1.1063x; 1.1063x over previous
#include <cuda_runtime.h>
#include <cuda_bf16.h>
#include <cstdint>

#define DIMC  512
#define NPOS  256
#define NB    2
#define NTAB  961
#define KDIM  512
#define KC    64                 // bf16 k per chunk = 128 bytes = SW128 row
#define LOG2E 1.4426950408889634f
#define SCALE 0.044194173824159216f   // 512^-0.5
#define DBLK  4
#define GSPLIT 4
#define GCH   (NPOS / GSPLIT)    // 64
#define QSPLIT 2
#define PSPLIT 4

// ---------------- scratch (device globals; no allocs) ----------------
__device__ float  g_qkv  [NB * 3 * DIMC * NPOS];               // [b][o][p] fp32
__device__ float  g_qpart[NB * QSPLIT * 3 * DIMC * NPOS];      // QKV split-K partials
__device__ float  g_part [NB * PSPLIT * DIMC * NPOS];          // proj split-K partials
__device__ float  g_bias [NPOS * NPOS];                        // biasT[g][h]*log2e
__device__ float2 g_pp   [NB * DIMC * NPOS * GSPLIT];          // attn partial (num,den)
__device__ __align__(16) __nv_bfloat16 g_wq_hi[3 * DIMC * KDIM];
__device__ __align__(16) __nv_bfloat16 g_wq_lo[3 * DIMC * KDIM];
__device__ __align__(16) __nv_bfloat16 g_wp_hi[DIMC * KDIM];
__device__ __align__(16) __nv_bfloat16 g_wp_lo[DIMC * KDIM];
__device__ __align__(16) __nv_bfloat16 g_xt_hi[NB * NPOS * KDIM];  // Xt[h][c]
__device__ __align__(16) __nv_bfloat16 g_xt_lo[NB * NPOS * KDIM];
__device__ __align__(16) __nv_bfloat16 g_ot_hi[NB * NPOS * KDIM];  // Ot[h][d]
__device__ __align__(16) __nv_bfloat16 g_ot_lo[NB * NPOS * KDIM];

// ---------------- helpers ----------------
__device__ __forceinline__ uint32_t smem_u32(const void* p) {
    uint32_t a;
    asm("{ .reg .u64 t; cvta.to.shared.u64 t, %1; cvt.u32.u64 %0, t; }" : "=r"(a) : "l"(p));
    return a;
}
#define SWZ128(off) ((off) ^ (((off) >> 3) & 0x70))

__device__ __forceinline__ void ldsm_x4(uint32_t* r, uint32_t addr) {
    asm volatile("ldmatrix.sync.aligned.m8n8.x4.shared.b16 {%0,%1,%2,%3}, [%4];"
                 : "=r"(r[0]), "=r"(r[1]), "=r"(r[2]), "=r"(r[3]) : "r"(addr));
}
__device__ __forceinline__ void mma_bf16(float* d, const uint32_t* a, const uint32_t* b) {
    asm volatile(
        "mma.sync.aligned.m16n8k16.row.col.f32.bf16.bf16.f32 "
        "{%0,%1,%2,%3}, {%4,%5,%6,%7}, {%8,%9}, {%0,%1,%2,%3};"
        : "+f"(d[0]), "+f"(d[1]), "+f"(d[2]), "+f"(d[3])
        : "r"(a[0]), "r"(a[1]), "r"(a[2]), "r"(a[3]), "r"(b[0]), "r"(b[1]));
}

// ---------------- prep: split weights (x4 vec), bias table, transpose x -----
__global__ __launch_bounds__(256) void prep(const float* __restrict__ x,
                                            const float* __restrict__ qkv_w,
                                            const float* __restrict__ proj_w,
                                            const float* __restrict__ rpb) {
    const int blk = blockIdx.x, t = threadIdx.x;
    const int NW1 = (3 * DIMC * KDIM) / 1024;       // 768  (x4 vectorized)
    const int NW2 = NW1 + (DIMC * KDIM) / 1024;     // +256
    const int NW3 = NW2 + (NPOS * NPOS) / 256;      // +256

    if (blk < NW2) {
        const bool isQ = blk < NW1;
        const float* W = isQ ? qkv_w : proj_w;
        __nv_bfloat16* Hi = isQ ? g_wq_hi : g_wp_hi;
        __nv_bfloat16* Lo = isQ ? g_wq_lo : g_wp_lo;
        long i = ((long)(isQ ? blk : blk - NW1) * 256 + t) * 4;
        float4 w = *(const float4*)(W + i);
        __nv_bfloat16 h0 = __float2bfloat16(w.x), h1 = __float2bfloat16(w.y);
        __nv_bfloat16 h2 = __float2bfloat16(w.z), h3 = __float2bfloat16(w.w);
        __nv_bfloat16 hv[4] = {h0, h1, h2, h3};
        __nv_bfloat16 lv[4] = {
            __float2bfloat16(w.x - __bfloat162float(h0)),
            __float2bfloat16(w.y - __bfloat162float(h1)),
            __float2bfloat16(w.z - __bfloat162float(h2)),
            __float2bfloat16(w.w - __bfloat162float(h3))};
        *(uint2*)(Hi + i) = *(const uint2*)hv;
        *(uint2*)(Lo + i) = *(const uint2*)lv;
    } else if (blk < NW3) {
        int i = (blk - NW2) * 256 + t;
        int g = i >> 8, h = i & 255;
        int v = ((h >> 4) - (g >> 4)) + ((h & 15) - (g & 15));
        g_bias[i] = rpb[(v + NTAB) % NTAB] * LOG2E;
    } else {
        // transpose x[b][c][h] -> Xt[b][h][c] (+ hi/lo split)
        int q = blk - NW3;                 // 0..255
        int b = q >> 7;
        int r = q & 127;
        int c0 = (r >> 3) * 32;
        int h0 = (r & 7) * 32;
        __shared__ float tile[32][33];
        int tx = t & 31, ty = t >> 5;
#pragma unroll
        for (int i = 0; i < 4; i++)
            tile[ty + 8 * i][tx] = (x + (long)b * DIMC * NPOS)
                                   [(long)(c0 + ty + 8 * i) * NPOS + h0 + tx];
        __syncthreads();
#pragma unroll
        for (int i = 0; i < 4; i++) {
            int h = h0 + ty + 8 * i, c = c0 + tx;
            float v = tile[tx][ty + 8 * i];
            __nv_bfloat16 hi = __float2bfloat16(v);
            long o = (long)b * NPOS * KDIM + (long)h * KDIM + c;
            g_xt_hi[o] = hi;
            g_xt_lo[o] = __float2bfloat16(v - __bfloat162float(hi));
        }
    }
}

// ---------------- mma.sync GEMM: C[m][n] = sum_k A[m][k]*B[n][k] ------------
#define SA_HI 0
#define SA_LO 8192
#define SB_HI 16384
#define SB_LO 24576

template<int SPLIT>
__global__ __launch_bounds__(256) void mma_gemm(
        const __nv_bfloat16* __restrict__ Ahi, const __nv_bfloat16* __restrict__ Alo,
        const __nv_bfloat16* __restrict__ Bhi, const __nv_bfloat16* __restrict__ Blo,
        long sB, float* __restrict__ C, long sC) {
    __shared__ __align__(1024) char smem[32768];
    const uint32_t sb = smem_u32(smem);
    const int t = threadIdx.x;
    const int lane = t & 31, wid = t >> 5;
    const int wm = wid & 1, wn = wid >> 1;       // 2 (M) x 4 (N)
    const int n0 = blockIdx.x * 64;
    const int m0 = blockIdx.y * 64;
    const int z  = blockIdx.z;
    const int b  = z / SPLIT;
    const int ks0 = z % SPLIT;
    const int nch = (KDIM / KC) / SPLIT;
    const int ch0 = ks0 * nch;

    const __nv_bfloat16* Ah = Ahi + (long)m0 * KDIM;
    const __nv_bfloat16* Al = Alo + (long)m0 * KDIM;
    const __nv_bfloat16* Bh = Bhi + (long)b * sB + (long)n0 * KDIM;
    const __nv_bfloat16* Bl = Blo + (long)b * sB + (long)n0 * KDIM;

    float ahh[2][2][4], ahl[2][2][4], alh[2][2][4];
#pragma unroll
    for (int i = 0; i < 2; i++)
#pragma unroll
        for (int j = 0; j < 2; j++)
#pragma unroll
            for (int r = 0; r < 4; r++) {
                ahh[i][j][r] = 0.f; ahl[i][j][r] = 0.f; alh[i][j][r] = 0.f;
            }

    int rowi[2], jci[2];
    uint32_t dsti[2];
#pragma unroll
    for (int i = 0; i < 2; i++) {
        int id = t + i * 256;
        rowi[i] = id >> 3; jci[i] = id & 7;
        dsti[i] = SWZ128((uint32_t)(rowi[i] * 128 + jci[i] * 16));
    }

    const int a_row  = wm * 32 + (lane & 15);
    const int a_colb = (lane >> 4) << 4;
    const int b_row  = wn * 16 + (lane & 7) + ((lane >> 4) << 3);
    const int b_colb = ((lane >> 3) & 1) << 4;

    uint4 pah[2], pal[2], pbh[2], pbl[2];
#pragma unroll
    for (int i = 0; i < 2; i++) {
        long go = (long)rowi[i] * KDIM + (long)ch0 * KC + jci[i] * 8;
        pah[i] = *(const uint4*)(Ah + go);
        pal[i] = *(const uint4*)(Al + go);
        pbh[i] = *(const uint4*)(Bh + go);
        pbl[i] = *(const uint4*)(Bl + go);
    }

    for (int ch = 0; ch < nch; ch++) {
#pragma unroll
        for (int i = 0; i < 2; i++) {
            *(uint4*)(smem + SA_HI + dsti[i]) = pah[i];
            *(uint4*)(smem + SA_LO + dsti[i]) = pal[i];
            *(uint4*)(smem + SB_HI + dsti[i]) = pbh[i];
            *(uint4*)(smem + SB_LO + dsti[i]) = pbl[i];
        }
        __syncthreads();

        if (ch + 1 < nch) {
            const long kb16 = (long)(ch0 + ch + 1) * KC;
#pragma unroll
            for (int i = 0; i < 2; i++) {
                long go = (long)rowi[i] * KDIM + kb16 + jci[i] * 8;
                pah[i] = *(const uint4*)(Ah + go);
                pal[i] = *(const uint4*)(Al + go);
                pbh[i] = *(const uint4*)(Bh + go);
                pbl[i] = *(const uint4*)(Bl + go);
            }
        }

#pragma unroll
        for (int kq = 0; kq < 4; kq++) {
            const int kb = kq * 32;
            uint32_t ah[2][4], al[2][4], bh[4], bl[4];
#pragma unroll
            for (int mi = 0; mi < 2; mi++) {
                uint32_t off = SWZ128((uint32_t)((a_row + mi * 16) * 128 + kb + a_colb));
                ldsm_x4(ah[mi], sb + SA_HI + off);
                ldsm_x4(al[mi], sb + SA_LO + off);
            }
            {
                uint32_t off = SWZ128((uint32_t)(b_row * 128 + kb + b_colb));
                ldsm_x4(bh, sb + SB_HI + off);
                ldsm_x4(bl, sb + SB_LO + off);
            }
#pragma unroll
            for (int mi = 0; mi < 2; mi++)
#pragma unroll
                for (int nj = 0; nj < 2; nj++) {
                    mma_bf16(ahh[mi][nj], ah[mi], &bh[nj * 2]);
                    mma_bf16(ahl[mi][nj], ah[mi], &bl[nj * 2]);
                    mma_bf16(alh[mi][nj], al[mi], &bh[nj * 2]);
                }
        }
        __syncthreads();
    }

    const int g = lane >> 2, tg = lane & 3;
#pragma unroll
    for (int mi = 0; mi < 2; mi++) {
        int mrow = m0 + wm * 32 + mi * 16 + g;
        float* Crow0 = C + (long)z * sC + (long)mrow * NPOS + n0 + wn * 16;
        float* Crow1 = Crow0 + 8 * NPOS;
#pragma unroll
        for (int nj = 0; nj < 2; nj++) {
            int c = nj * 8 + tg * 2;
            Crow0[c]     = ahh[mi][nj][0] + ahl[mi][nj][0] + alh[mi][nj][0];
            Crow0[c + 1] = ahh[mi][nj][1] + ahl[mi][nj][1] + alh[mi][nj][1];
            Crow1[c]     = ahh[mi][nj][2] + ahl[mi][nj][2] + alh[mi][nj][2];
            Crow1[c + 1] = ahh[mi][nj][3] + ahl[mi][nj][3] + alh[mi][nj][3];
        }
    }
}

// ---------------- deterministic split-K reduce (+bias) ----------------------
template<int SPLIT>
__global__ __launch_bounds__(256) void splitk_reduce(const float* __restrict__ part,
                                                     const float* __restrict__ bias,
                                                     float* __restrict__ out, int Mrows) {
    const long MN = (long)Mrows * NPOS;
    const long idx = ((long)blockIdx.x * 256 + threadIdx.x) * 4;
    const int b  = (int)(idx / MN);
    const long mn = idx - (long)b * MN;
    const int m  = (int)(mn / NPOS);

    const float* p0 = part + ((long)b * SPLIT) * MN + mn;
    float4 s = *(const float4*)p0;
#pragma unroll
    for (int k = 1; k < SPLIT; k++) {
        float4 q = *(const float4*)(p0 + (long)k * MN);
        s.x += q.x; s.y += q.y; s.z += q.z; s.w += q.w;
    }
    float bb = bias[m];
    s.x += bb; s.y += bb; s.z += bb; s.w += bb;
    *(float4*)(out + idx) = s;
}

// ---------------- per-channel attention: g-split partial pass ---------------
// CTA = (d-block of 4, g-chunk of 64, b). Thread h accumulates partial
// (num, den) over its g-chunk for 4 channels. 1024 CTAs total.
__global__ __launch_bounds__(256) void chan_attn_part() {
    const int d0 = blockIdx.x * DBLK;
    const int s  = blockIdx.y;
    const int b  = blockIdx.z;
    const int h  = threadIdx.x;
    const int g0 = s * GCH;

    const float* base = g_qkv + (long)b * 3 * DIMC * NPOS;
    __shared__ float2 skv[DBLK][GCH];

    // stage k,v for this (d-block, g-chunk): DBLK*GCH = 256 entries
    {
        int d = h / GCH, gg = h % GCH;
        float kk = base[(long)(DIMC     + d0 + d) * NPOS + g0 + gg];
        float vv = base[(long)(2 * DIMC + d0 + d) * NPOS + g0 + gg];
        skv[d][gg] = make_float2(kk, vv);
    }

    float a[DBLK], num[DBLK], den[DBLK];
#pragma unroll
    for (int d = 0; d < DBLK; d++) {
        a[d]   = base[(long)(d0 + d) * NPOS + h] * (SCALE * LOG2E);
        num[d] = 0.f;
        den[d] = 0.f;
    }
    __syncthreads();

    const float* bp = g_bias + (long)g0 * NPOS + h;
#pragma unroll 8
    for (int gg = 0; gg < GCH; gg++) {
        float bb = __ldg(bp);
        bp += NPOS;
#pragma unroll
        for (int d = 0; d < DBLK; d++) {
            float2 kv = skv[d][gg];
            float e = exp2f(fmaf(a[d], kv.x, bb));
            num[d] = fmaf(e, kv.y, num[d]);
            den[d] += e;
        }
    }

#pragma unroll
    for (int d = 0; d < DBLK; d++)
        g_pp[(((long)b * DIMC + d0 + d) * NPOS + h) * GSPLIT + s] =
            make_float2(num[d], den[d]);
}

// ---------------- combine partials -> transposed hi/lo bf16 output ----------
// thread = (b, h, group of 8 d). Fixed-order sums (deterministic).
__global__ __launch_bounds__(256) void chan_attn_comb() {
    const int idx = blockIdx.x * 256 + threadIdx.x;     // 0..32767
    const int b  = idx >> 14;
    const int r  = idx & 16383;
    const int h  = r >> 6;
    const int dg = (r & 63) * 8;

    __nv_bfloat16 oh[8], ol[8];
#pragma unroll
    for (int d = 0; d < 8; d++) {
        const float2* p = g_pp + (((long)b * DIMC + dg + d) * NPOS + h) * GSPLIT;
        float num = 0.f, den = 0.f;
#pragma unroll
        for (int s = 0; s < GSPLIT; s++) {
            float2 q = p[s];
            num += q.x; den += q.y;
        }
        float o = num / den;
        oh[d] = __float2bfloat16(o);
        ol[d] = __float2bfloat16(o - __bfloat162float(oh[d]));
    }
    long off = ((long)b * NPOS + h) * KDIM + dg;
    *(uint4*)(g_ot_hi + off) = *(const uint4*)oh;
    *(uint4*)(g_ot_lo + off) = *(const uint4*)ol;
}

// ---------------------------------------------------------------------------
extern "C" void kernel_launch(void* const* d_in, const int* in_sizes, int n_in,
                              void* d_out, int out_size) {
    const float* x      = (const float*)d_in[0];
    const float* qkv_w  = (const float*)d_in[1];
    const float* qkv_b  = (const float*)d_in[2];
    const float* proj_w = (const float*)d_in[3];
    const float* proj_b = (const float*)d_in[4];
    const float* rpb    = (const float*)d_in[5];
    float* out = (float*)d_out;

    float *qkv_ptr, *qpart_ptr, *part_ptr;
    __nv_bfloat16 *wqh, *wql, *wph, *wpl, *xth, *xtl, *oth, *otl;
    cudaGetSymbolAddress((void**)&qkv_ptr,  g_qkv);
    cudaGetSymbolAddress((void**)&qpart_ptr, g_qpart);
    cudaGetSymbolAddress((void**)&part_ptr, g_part);
    cudaGetSymbolAddress((void**)&wqh, g_wq_hi);
    cudaGetSymbolAddress((void**)&wql, g_wq_lo);
    cudaGetSymbolAddress((void**)&wph, g_wp_hi);
    cudaGetSymbolAddress((void**)&wpl, g_wp_lo);
    cudaGetSymbolAddress((void**)&xth, g_xt_hi);
    cudaGetSymbolAddress((void**)&xtl, g_xt_lo);
    cudaGetSymbolAddress((void**)&oth, g_ot_hi);
    cudaGetSymbolAddress((void**)&otl, g_ot_lo);

    // 1) prep: weight split + bias table + x transpose/split
    prep<<<768 + 256 + 256 + 256, 256>>>(x, qkv_w, proj_w, rpb);

    // 2) QKV split-K x2 (384 CTAs) + reduce(+bias) -> g_qkv fp32 [o][p]
    {
        dim3 grid(NPOS / 64, (3 * DIMC) / 64, NB * QSPLIT);  // (4, 24, 4)
        mma_gemm<QSPLIT><<<grid, 256>>>(wqh, wql, xth, xtl,
                                        (long)NPOS * KDIM,
                                        qpart_ptr, (long)3 * DIMC * NPOS);
        splitk_reduce<QSPLIT><<<(NB * 3 * DIMC * NPOS / 4) / 256, 256>>>(
            qpart_ptr, qkv_b, qkv_ptr, 3 * DIMC);
    }

    // 3) per-channel attention: partial (1024 CTAs) + combine (128 CTAs)
    {
        dim3 grid(DIMC / DBLK, GSPLIT, NB);                  // (128, 4, 2)
        chan_attn_part<<<grid, 256>>>();
        chan_attn_comb<<<(NB * NPOS * 64) / 256, 256>>>();   // 128 CTAs
    }

    // 4) out = proj_w * Ot^T (+b): split-K x4 (256 CTAs) + reduce
    {
        dim3 grid(NPOS / 64, DIMC / 64, NB * PSPLIT);        // (4, 8, 8)
        mma_gemm<PSPLIT><<<grid, 256>>>(wph, wpl, oth, otl,
                                        (long)NPOS * KDIM,
                                        part_ptr, (long)DIMC * NPOS);
        splitk_reduce<PSPLIT><<<(NB * DIMC * NPOS / 4) / 256, 256>>>(
            part_ptr, proj_b, out, DIMC);
    }
}

// round 17
// speedup vs baseline: 1.1082x; 1.0017x over previous
#include <cuda_runtime.h>
#include <cuda_bf16.h>
#include <cstdint>

#define DIMC  512
#define NPOS  256
#define NB    2
#define NTAB  961
#define KDIM  512
#define KC    64                 // bf16 k per chunk = 128 bytes = SW128 row
#define LOG2E 1.4426950408889634f
#define SCALE 0.044194173824159216f   // 512^-0.5
#define DBLK  4
#define GSPLIT 4
#define GCH   (NPOS / GSPLIT)    // 64
#define QSPLIT 2
#define PSPLIT 4

// ---------------- scratch (device globals; no allocs) ----------------
__device__ float  g_qpart[NB * QSPLIT * 3 * DIMC * NPOS];      // QKV split-K partials
__device__ float  g_part [NB * PSPLIT * DIMC * NPOS];          // proj split-K partials
__device__ float  g_bias [NPOS * NPOS];                        // biasT[g][h]*log2e
__device__ float2 g_pp   [NB * DIMC * NPOS * GSPLIT];          // attn partial (num,den)
__device__ __align__(16) __nv_bfloat16 g_wq_hi[3 * DIMC * KDIM];
__device__ __align__(16) __nv_bfloat16 g_wq_lo[3 * DIMC * KDIM];
__device__ __align__(16) __nv_bfloat16 g_wp_hi[DIMC * KDIM];
__device__ __align__(16) __nv_bfloat16 g_wp_lo[DIMC * KDIM];
__device__ __align__(16) __nv_bfloat16 g_xt_hi[NB * NPOS * KDIM];  // Xt[h][c]
__device__ __align__(16) __nv_bfloat16 g_xt_lo[NB * NPOS * KDIM];
__device__ __align__(16) __nv_bfloat16 g_ot_hi[NB * NPOS * KDIM];  // Ot[h][d]
__device__ __align__(16) __nv_bfloat16 g_ot_lo[NB * NPOS * KDIM];

// ---------------- helpers ----------------
__device__ __forceinline__ uint32_t smem_u32(const void* p) {
    uint32_t a;
    asm("{ .reg .u64 t; cvta.to.shared.u64 t, %1; cvt.u32.u64 %0, t; }" : "=r"(a) : "l"(p));
    return a;
}
#define SWZ128(off) ((off) ^ (((off) >> 3) & 0x70))

__device__ __forceinline__ void ldsm_x4(uint32_t* r, uint32_t addr) {
    asm volatile("ldmatrix.sync.aligned.m8n8.x4.shared.b16 {%0,%1,%2,%3}, [%4];"
                 : "=r"(r[0]), "=r"(r[1]), "=r"(r[2]), "=r"(r[3]) : "r"(addr));
}
__device__ __forceinline__ void mma_bf16(float* d, const uint32_t* a, const uint32_t* b) {
    asm volatile(
        "mma.sync.aligned.m16n8k16.row.col.f32.bf16.bf16.f32 "
        "{%0,%1,%2,%3}, {%4,%5,%6,%7}, {%8,%9}, {%0,%1,%2,%3};"
        : "+f"(d[0]), "+f"(d[1]), "+f"(d[2]), "+f"(d[3])
        : "r"(a[0]), "r"(a[1]), "r"(a[2]), "r"(a[3]), "r"(b[0]), "r"(b[1]));
}

// ---------------- prep: split weights (x4 vec), bias table, transpose x -----
__global__ __launch_bounds__(256) void prep(const float* __restrict__ x,
                                            const float* __restrict__ qkv_w,
                                            const float* __restrict__ proj_w,
                                            const float* __restrict__ rpb) {
    const int blk = blockIdx.x, t = threadIdx.x;
    const int NW1 = (3 * DIMC * KDIM) / 1024;       // 768  (x4 vectorized)
    const int NW2 = NW1 + (DIMC * KDIM) / 1024;     // +256
    const int NW3 = NW2 + (NPOS * NPOS) / 256;      // +256

    if (blk < NW2) {
        const bool isQ = blk < NW1;
        const float* W = isQ ? qkv_w : proj_w;
        __nv_bfloat16* Hi = isQ ? g_wq_hi : g_wp_hi;
        __nv_bfloat16* Lo = isQ ? g_wq_lo : g_wp_lo;
        long i = ((long)(isQ ? blk : blk - NW1) * 256 + t) * 4;
        float4 w = *(const float4*)(W + i);
        __nv_bfloat16 h0 = __float2bfloat16(w.x), h1 = __float2bfloat16(w.y);
        __nv_bfloat16 h2 = __float2bfloat16(w.z), h3 = __float2bfloat16(w.w);
        __nv_bfloat16 hv[4] = {h0, h1, h2, h3};
        __nv_bfloat16 lv[4] = {
            __float2bfloat16(w.x - __bfloat162float(h0)),
            __float2bfloat16(w.y - __bfloat162float(h1)),
            __float2bfloat16(w.z - __bfloat162float(h2)),
            __float2bfloat16(w.w - __bfloat162float(h3))};
        *(uint2*)(Hi + i) = *(const uint2*)hv;
        *(uint2*)(Lo + i) = *(const uint2*)lv;
    } else if (blk < NW3) {
        int i = (blk - NW2) * 256 + t;
        int g = i >> 8, h = i & 255;
        int v = ((h >> 4) - (g >> 4)) + ((h & 15) - (g & 15));
        g_bias[i] = rpb[(v + NTAB) % NTAB] * LOG2E;
    } else {
        // transpose x[b][c][h] -> Xt[b][h][c] (+ hi/lo split)
        int q = blk - NW3;                 // 0..255
        int b = q >> 7;
        int r = q & 127;
        int c0 = (r >> 3) * 32;
        int h0 = (r & 7) * 32;
        __shared__ float tile[32][33];
        int tx = t & 31, ty = t >> 5;
#pragma unroll
        for (int i = 0; i < 4; i++)
            tile[ty + 8 * i][tx] = (x + (long)b * DIMC * NPOS)
                                   [(long)(c0 + ty + 8 * i) * NPOS + h0 + tx];
        __syncthreads();
#pragma unroll
        for (int i = 0; i < 4; i++) {
            int h = h0 + ty + 8 * i, c = c0 + tx;
            float v = tile[tx][ty + 8 * i];
            __nv_bfloat16 hi = __float2bfloat16(v);
            long o = (long)b * NPOS * KDIM + (long)h * KDIM + c;
            g_xt_hi[o] = hi;
            g_xt_lo[o] = __float2bfloat16(v - __bfloat162float(hi));
        }
    }
}

// ---------------- mma.sync GEMM: C[m][n] = sum_k A[m][k]*B[n][k] ------------
#define SA_HI 0
#define SA_LO 8192
#define SB_HI 16384
#define SB_LO 24576

template<int SPLIT>
__global__ __launch_bounds__(256) void mma_gemm(
        const __nv_bfloat16* __restrict__ Ahi, const __nv_bfloat16* __restrict__ Alo,
        const __nv_bfloat16* __restrict__ Bhi, const __nv_bfloat16* __restrict__ Blo,
        long sB, float* __restrict__ C, long sC) {
    __shared__ __align__(1024) char smem[32768];
    const uint32_t sb = smem_u32(smem);
    const int t = threadIdx.x;
    const int lane = t & 31, wid = t >> 5;
    const int wm = wid & 1, wn = wid >> 1;       // 2 (M) x 4 (N)
    const int n0 = blockIdx.x * 64;
    const int m0 = blockIdx.y * 64;
    const int z  = blockIdx.z;
    const int b  = z / SPLIT;
    const int ks0 = z % SPLIT;
    const int nch = (KDIM / KC) / SPLIT;
    const int ch0 = ks0 * nch;

    const __nv_bfloat16* Ah = Ahi + (long)m0 * KDIM;
    const __nv_bfloat16* Al = Alo + (long)m0 * KDIM;
    const __nv_bfloat16* Bh = Bhi + (long)b * sB + (long)n0 * KDIM;
    const __nv_bfloat16* Bl = Blo + (long)b * sB + (long)n0 * KDIM;

    float ahh[2][2][4], ahl[2][2][4], alh[2][2][4];
#pragma unroll
    for (int i = 0; i < 2; i++)
#pragma unroll
        for (int j = 0; j < 2; j++)
#pragma unroll
            for (int r = 0; r < 4; r++) {
                ahh[i][j][r] = 0.f; ahl[i][j][r] = 0.f; alh[i][j][r] = 0.f;
            }

    int rowi[2], jci[2];
    uint32_t dsti[2];
#pragma unroll
    for (int i = 0; i < 2; i++) {
        int id = t + i * 256;
        rowi[i] = id >> 3; jci[i] = id & 7;
        dsti[i] = SWZ128((uint32_t)(rowi[i] * 128 + jci[i] * 16));
    }

    const int a_row  = wm * 32 + (lane & 15);
    const int a_colb = (lane >> 4) << 4;
    const int b_row  = wn * 16 + (lane & 7) + ((lane >> 4) << 3);
    const int b_colb = ((lane >> 3) & 1) << 4;

    uint4 pah[2], pal[2], pbh[2], pbl[2];
#pragma unroll
    for (int i = 0; i < 2; i++) {
        long go = (long)rowi[i] * KDIM + (long)ch0 * KC + jci[i] * 8;
        pah[i] = *(const uint4*)(Ah + go);
        pal[i] = *(const uint4*)(Al + go);
        pbh[i] = *(const uint4*)(Bh + go);
        pbl[i] = *(const uint4*)(Bl + go);
    }

    for (int ch = 0; ch < nch; ch++) {
#pragma unroll
        for (int i = 0; i < 2; i++) {
            *(uint4*)(smem + SA_HI + dsti[i]) = pah[i];
            *(uint4*)(smem + SA_LO + dsti[i]) = pal[i];
            *(uint4*)(smem + SB_HI + dsti[i]) = pbh[i];
            *(uint4*)(smem + SB_LO + dsti[i]) = pbl[i];
        }
        __syncthreads();

        if (ch + 1 < nch) {
            const long kb16 = (long)(ch0 + ch + 1) * KC;
#pragma unroll
            for (int i = 0; i < 2; i++) {
                long go = (long)rowi[i] * KDIM + kb16 + jci[i] * 8;
                pah[i] = *(const uint4*)(Ah + go);
                pal[i] = *(const uint4*)(Al + go);
                pbh[i] = *(const uint4*)(Bh + go);
                pbl[i] = *(const uint4*)(Bl + go);
            }
        }

#pragma unroll
        for (int kq = 0; kq < 4; kq++) {
            const int kb = kq * 32;
            uint32_t ah[2][4], al[2][4], bh[4], bl[4];
#pragma unroll
            for (int mi = 0; mi < 2; mi++) {
                uint32_t off = SWZ128((uint32_t)((a_row + mi * 16) * 128 + kb + a_colb));
                ldsm_x4(ah[mi], sb + SA_HI + off);
                ldsm_x4(al[mi], sb + SA_LO + off);
            }
            {
                uint32_t off = SWZ128((uint32_t)(b_row * 128 + kb + b_colb));
                ldsm_x4(bh, sb + SB_HI + off);
                ldsm_x4(bl, sb + SB_LO + off);
            }
#pragma unroll
            for (int mi = 0; mi < 2; mi++)
#pragma unroll
                for (int nj = 0; nj < 2; nj++) {
                    mma_bf16(ahh[mi][nj], ah[mi], &bh[nj * 2]);
                    mma_bf16(ahl[mi][nj], ah[mi], &bl[nj * 2]);
                    mma_bf16(alh[mi][nj], al[mi], &bh[nj * 2]);
                }
        }
        __syncthreads();
    }

    const int g = lane >> 2, tg = lane & 3;
#pragma unroll
    for (int mi = 0; mi < 2; mi++) {
        int mrow = m0 + wm * 32 + mi * 16 + g;
        float* Crow0 = C + (long)z * sC + (long)mrow * NPOS + n0 + wn * 16;
        float* Crow1 = Crow0 + 8 * NPOS;
#pragma unroll
        for (int nj = 0; nj < 2; nj++) {
            int c = nj * 8 + tg * 2;
            Crow0[c]     = ahh[mi][nj][0] + ahl[mi][nj][0] + alh[mi][nj][0];
            Crow0[c + 1] = ahh[mi][nj][1] + ahl[mi][nj][1] + alh[mi][nj][1];
            Crow1[c]     = ahh[mi][nj][2] + ahl[mi][nj][2] + alh[mi][nj][2];
            Crow1[c + 1] = ahh[mi][nj][3] + ahl[mi][nj][3] + alh[mi][nj][3];
        }
    }
}

// ---------------- deterministic split-K reduce (+bias) ----------------------
template<int SPLIT>
__global__ __launch_bounds__(256) void splitk_reduce(const float* __restrict__ part,
                                                     const float* __restrict__ bias,
                                                     float* __restrict__ out, int Mrows) {
    const long MN = (long)Mrows * NPOS;
    const long idx = ((long)blockIdx.x * 256 + threadIdx.x) * 4;
    const int b  = (int)(idx / MN);
    const long mn = idx - (long)b * MN;
    const int m  = (int)(mn / NPOS);

    const float* p0 = part + ((long)b * SPLIT) * MN + mn;
    float4 s = *(const float4*)p0;
#pragma unroll
    for (int k = 1; k < SPLIT; k++) {
        float4 q = *(const float4*)(p0 + (long)k * MN);
        s.x += q.x; s.y += q.y; s.z += q.z; s.w += q.w;
    }
    float bb = bias[m];
    s.x += bb; s.y += bb; s.z += bb; s.w += bb;
    *(float4*)(out + idx) = s;
}

// ---------------- per-channel attention: g-split partial pass ---------------
// CTA = (d-block of 4, g-chunk of 64, b). Fuses the QKV split-K reduce:
// q/k/v = qpart0 + qpart1 + qkv_b (same order as the old reduce kernel).
// skv laid out [gg][d] so the inner loop does 2x LDS.128 broadcast per gg.
__global__ __launch_bounds__(256) void chan_attn_part(const float* __restrict__ qkv_b) {
    const int d0 = blockIdx.x * DBLK;
    const int s  = blockIdx.y;
    const int b  = blockIdx.z;
    const int h  = threadIdx.x;
    const int g0 = s * GCH;

    const long S = (long)3 * DIMC * NPOS;
    const float* p0 = g_qpart + (long)b * QSPLIT * S;
    const float* p1 = p0 + S;

    __shared__ float2 skv[GCH][DBLK];    // [gg][d] -> (k,v); 32B per gg row

    // stage k,v with fused split-K reduce + bias
    {
        int gg = h >> 2, d = h & 3;
        long ko = (long)(DIMC     + d0 + d) * NPOS + g0 + gg;
        long vo = (long)(2 * DIMC + d0 + d) * NPOS + g0 + gg;
        float kk = p0[ko] + p1[ko] + qkv_b[DIMC + d0 + d];
        float vv = p0[vo] + p1[vo] + qkv_b[2 * DIMC + d0 + d];
        skv[gg][d] = make_float2(kk, vv);
    }

    float a[DBLK], num[DBLK], den[DBLK];
#pragma unroll
    for (int d = 0; d < DBLK; d++) {
        long qo = (long)(d0 + d) * NPOS + h;
        a[d] = (p0[qo] + p1[qo] + qkv_b[d0 + d]) * (SCALE * LOG2E);
        num[d] = 0.f;
        den[d] = 0.f;
    }
    __syncthreads();

    const float* bp = g_bias + (long)g0 * NPOS + h;
#pragma unroll 4
    for (int gg = 0; gg < GCH; gg++) {
        float bb = __ldg(bp);
        bp += NPOS;
        float4 kv01 = *(const float4*)&skv[gg][0];   // (k0,v0,k1,v1)
        float4 kv23 = *(const float4*)&skv[gg][2];   // (k2,v2,k3,v3)
        float e0 = exp2f(fmaf(a[0], kv01.x, bb));
        float e1 = exp2f(fmaf(a[1], kv01.z, bb));
        float e2 = exp2f(fmaf(a[2], kv23.x, bb));
        float e3 = exp2f(fmaf(a[3], kv23.z, bb));
        num[0] = fmaf(e0, kv01.y, num[0]); den[0] += e0;
        num[1] = fmaf(e1, kv01.w, num[1]); den[1] += e1;
        num[2] = fmaf(e2, kv23.y, num[2]); den[2] += e2;
        num[3] = fmaf(e3, kv23.w, num[3]); den[3] += e3;
    }

#pragma unroll
    for (int d = 0; d < DBLK; d++)
        g_pp[(((long)b * DIMC + d0 + d) * NPOS + h) * GSPLIT + s] =
            make_float2(num[d], den[d]);
}

// ---------------- combine partials -> transposed hi/lo bf16 output ----------
__global__ __launch_bounds__(256) void chan_attn_comb() {
    const int idx = blockIdx.x * 256 + threadIdx.x;     // 0..32767
    const int b  = idx >> 14;
    const int r  = idx & 16383;
    const int h  = r >> 6;
    const int dg = (r & 63) * 8;

    __nv_bfloat16 oh[8], ol[8];
#pragma unroll
    for (int d = 0; d < 8; d++) {
        const float2* p = g_pp + (((long)b * DIMC + dg + d) * NPOS + h) * GSPLIT;
        float num = 0.f, den = 0.f;
#pragma unroll
        for (int s = 0; s < GSPLIT; s++) {
            float2 q = p[s];
            num += q.x; den += q.y;
        }
        float o = num / den;
        oh[d] = __float2bfloat16(o);
        ol[d] = __float2bfloat16(o - __bfloat162float(oh[d]));
    }
    long off = ((long)b * NPOS + h) * KDIM + dg;
    *(uint4*)(g_ot_hi + off) = *(const uint4*)oh;
    *(uint4*)(g_ot_lo + off) = *(const uint4*)ol;
}

// ---------------------------------------------------------------------------
extern "C" void kernel_launch(void* const* d_in, const int* in_sizes, int n_in,
                              void* d_out, int out_size) {
    const float* x      = (const float*)d_in[0];
    const float* qkv_w  = (const float*)d_in[1];
    const float* qkv_b  = (const float*)d_in[2];
    const float* proj_w = (const float*)d_in[3];
    const float* proj_b = (const float*)d_in[4];
    const float* rpb    = (const float*)d_in[5];
    float* out = (float*)d_out;

    float *qpart_ptr, *part_ptr;
    __nv_bfloat16 *wqh, *wql, *wph, *wpl, *xth, *xtl, *oth, *otl;
    cudaGetSymbolAddress((void**)&qpart_ptr, g_qpart);
    cudaGetSymbolAddress((void**)&part_ptr, g_part);
    cudaGetSymbolAddress((void**)&wqh, g_wq_hi);
    cudaGetSymbolAddress((void**)&wql, g_wq_lo);
    cudaGetSymbolAddress((void**)&wph, g_wp_hi);
    cudaGetSymbolAddress((void**)&wpl, g_wp_lo);
    cudaGetSymbolAddress((void**)&xth, g_xt_hi);
    cudaGetSymbolAddress((void**)&xtl, g_xt_lo);
    cudaGetSymbolAddress((void**)&oth, g_ot_hi);
    cudaGetSymbolAddress((void**)&otl, g_ot_lo);

    // 1) prep: weight split + bias table + x transpose/split
    prep<<<768 + 256 + 256 + 256, 256>>>(x, qkv_w, proj_w, rpb);

    // 2) QKV split-K x2 (384 CTAs) -> partials only (reduce fused into attn)
    {
        dim3 grid(NPOS / 64, (3 * DIMC) / 64, NB * QSPLIT);  // (4, 24, 4)
        mma_gemm<QSPLIT><<<grid, 256>>>(wqh, wql, xth, xtl,
                                        (long)NPOS * KDIM,
                                        qpart_ptr, (long)3 * DIMC * NPOS);
    }

    // 3) per-channel attention: partial (1024 CTAs, fused QKV reduce) + comb
    {
        dim3 grid(DIMC / DBLK, GSPLIT, NB);                  // (128, 4, 2)
        chan_attn_part<<<grid, 256>>>(qkv_b);
        chan_attn_comb<<<(NB * NPOS * 64) / 256, 256>>>();   // 128 CTAs
    }

    // 4) out = proj_w * Ot^T (+b): split-K x4 (256 CTAs) + reduce
    {
        dim3 grid(NPOS / 64, DIMC / 64, NB * PSPLIT);        // (4, 8, 8)
        mma_gemm<PSPLIT><<<grid, 256>>>(wph, wpl, oth, otl,
                                        (long)NPOS * KDIM,
                                        part_ptr, (long)DIMC * NPOS);
        splitk_reduce<PSPLIT><<<(NB * DIMC * NPOS / 4) / 256, 256>>>(
            part_ptr, proj_b, out, DIMC);
    }
}